// round 14
// baseline (speedup 1.0000x reference)
#include <cuda_runtime.h>
#include <cuda_fp16.h>
#include <math.h>
#include <stdint.h>

#define NN 50000
#define NE 800000
#define NT 17

// ---------------- scratch ----------------
__device__ float    g_nf[NN * 64];
__device__ float    g_aggr[NN * 64];
__device__ float    g_uv[(size_t)NN * 256];
__device__ __half   g_efh[(size_t)NE * 64];
__device__ __half   g_efl[(size_t)NE * 64];
__device__ float    g_emb[NN * 64];
__device__ float    g_scores[NE];
__device__ int      g_seg[NE];
__device__ float    g_epred[NE];
__device__ unsigned g_mx[NN * NT];
__device__ float    g_denom[NN * NT];
__device__ int      g_types[NN];
__device__ uint4    g_w1cf[4 * 16 * 32];
__device__ uint4    g_w2f[8 * 8 * 32];
__device__ uint4    g_wcatf[4 * 32 * 32];
__device__ uint4    g_nuf[8 * 8 * 32];
__device__ uint4    g_ne1f[4 * 8 * 32];
__device__ uint4    g_ne2f[4 * 8 * 32];
__device__ uint4    g_ee1f[4 * 8 * 32];
__device__ uint4    g_ee2f[4 * 8 * 32];
__device__ uint4    g_ec1f[4 * 8 * 32];
__device__ uint4    g_cef[4 * 8 * 32];

__device__ __forceinline__ unsigned ordf(float f) {
    unsigned u = __float_as_uint(f);
    return (u & 0x80000000u) ? ~u : (u | 0x80000000u);
}
__device__ __forceinline__ float deord(unsigned u) {
    return (u & 0x80000000u) ? __uint_as_float(u ^ 0x80000000u) : __uint_as_float(~u);
}

__device__ __forceinline__ unsigned pk(__half a, __half b) {
    return (unsigned)__half_as_ushort(a) | ((unsigned)__half_as_ushort(b) << 16);
}
__device__ __forceinline__ void split2(float x, float y, unsigned& hi, unsigned& lo) {
    __half hx = __float2half_rn(x), hy = __float2half_rn(y);
    float rx = x - __half2float(hx), ry = y - __half2float(hy);
    hi = pk(hx, hy);
    lo = pk(__float2half_rn(rx), __float2half_rn(ry));
}

__device__ __forceinline__ void mma_f16(float* d, const unsigned* a, unsigned b0, unsigned b1) {
    asm volatile(
        "mma.sync.aligned.m16n8k16.row.col.f32.f16.f16.f32 "
        "{%0,%1,%2,%3}, {%4,%5,%6,%7}, {%8,%9}, {%0,%1,%2,%3};"
        : "+f"(d[0]), "+f"(d[1]), "+f"(d[2]), "+f"(d[3])
        : "r"(a[0]), "r"(a[1]), "r"(a[2]), "r"(a[3]), "r"(b0), "r"(b1));
}

#define E_STRIDE 72

__device__ __forceinline__ void load_afrag(const __half* A_hi, const __half* A_lo,
                                           int row0, int k0, unsigned* ah, unsigned* al) {
    ah[0] = *(const unsigned*)(A_hi + row0 * E_STRIDE + k0);
    ah[1] = *(const unsigned*)(A_hi + (row0 + 8) * E_STRIDE + k0);
    ah[2] = *(const unsigned*)(A_hi + row0 * E_STRIDE + k0 + 8);
    ah[3] = *(const unsigned*)(A_hi + (row0 + 8) * E_STRIDE + k0 + 8);
    al[0] = *(const unsigned*)(A_lo + row0 * E_STRIDE + k0);
    al[1] = *(const unsigned*)(A_lo + (row0 + 8) * E_STRIDE + k0);
    al[2] = *(const unsigned*)(A_lo + row0 * E_STRIDE + k0 + 8);
    al[3] = *(const unsigned*)(A_lo + (row0 + 8) * E_STRIDE + k0 + 8);
}

__device__ __forceinline__ void stage_split64(const float* __restrict__ X, int r0, int rows,
                                              __half* A_hi, __half* A_lo, int tid) {
    const int r = tid >> 1, h = tid & 1;
    int gr = min(r0 + r, rows - 1);
    const float* rowp = X + (size_t)gr * 64 + h * 32;
    #pragma unroll
    for (int j = 0; j < 8; ++j) {
        float4 v = *(const float4*)(rowp + j * 4);
        int col = h * 32 + j * 4;
        unsigned h0, l0, h1, l1;
        split2(v.x, v.y, h0, l0);
        split2(v.z, v.w, h1, l1);
        *(uint2*)(A_hi + r * E_STRIDE + col) = make_uint2(h0, h1);
        *(uint2*)(A_lo + r * E_STRIDE + col) = make_uint2(l0, l1);
    }
}

// Build A-frags (K=16 chunk kc) from a reg-resident [8][4] D-frag tile
__device__ __forceinline__ void afrag_from_regs(const float df0[4], const float df1[4],
                                                unsigned* ah, unsigned* al) {
    split2(df0[0], df0[1], ah[0], al[0]);
    split2(df0[2], df0[3], ah[1], al[1]);
    split2(df1[0], df1[1], ah[2], al[2]);
    split2(df1[2], df1[3], ah[3], al[3]);
}

// UV from reg-resident nf tile d[8][4] (bias already applied); writes uv rows
__device__ __forceinline__ void uv_from_regs(const float d[8][4],
                                             const uint4* __restrict__ wcatf,
                                             float* __restrict__ uv,
                                             int row0, int row1, int lc, int lane, int rows) {
    #pragma unroll
    for (int half = 0; half < 2; ++half) {
        float duv[16][4];
        #pragma unroll
        for (int nt = 0; nt < 16; ++nt)
            #pragma unroll
            for (int j = 0; j < 4; ++j) duv[nt][j] = 0.f;
        #pragma unroll
        for (int kc = 0; kc < 4; ++kc) {
            unsigned ah[4], al[4];
            afrag_from_regs(d[2 * kc], d[2 * kc + 1], ah, al);
            #pragma unroll
            for (int nt = 0; nt < 16; ++nt) {
                uint4 w = wcatf[(kc * 32 + half * 16 + nt) * 32 + lane];
                mma_f16(duv[nt], ah, w.x, w.y);
                mma_f16(duv[nt], al, w.x, w.y);
                mma_f16(duv[nt], ah, w.z, w.w);
            }
        }
        int cb = half * 128;
        #pragma unroll
        for (int nt = 0; nt < 16; ++nt) {
            int col = cb + nt * 8 + lc * 2;
            if (row0 < rows)
                *(float2*)(uv + (size_t)row0 * 256 + col) = make_float2(duv[nt][0], duv[nt][1]);
            if (row1 < rows)
                *(float2*)(uv + (size_t)row1 * 256 + col) = make_float2(duv[nt][2], duv[nt][3]);
        }
    }
}

// =====================================================================
// Weight prep (single fused launch, 64 blocks x 256)
// =====================================================================
__device__ __forceinline__ void prep_one(const float* __restrict__ W, uint4* __restrict__ out,
                                         int NTILES, int Ncols, int i) {
    int lane = i & 31, nt = (i >> 5) % NTILES, kc = i / (32 * NTILES);
    int k0 = kc * 16 + (lane & 3) * 2;
    int n = nt * 8 + (lane >> 2);
    float v00 = W[(k0 + 0) * Ncols + n];
    float v01 = W[(k0 + 1) * Ncols + n];
    float v10 = W[(k0 + 8) * Ncols + n];
    float v11 = W[(k0 + 9) * Ncols + n];
    uint4 o;
    split2(v00, v01, o.x, o.z);
    split2(v10, v11, o.y, o.w);
    out[i] = o;
}

__global__ void prep_all_kernel(
    const float* me_w1, const float* me_w2, const float* nu_w1,
    const float* ne_w1, const float* ne_w2, const float* ee_w1,
    const float* ee_w2, const float* ec_w1, const float* ce_w,
    uint4* w1cf, uint4* w2f, uint4* wcatf, uint4* nuf,
    uint4* ne1f, uint4* ne2f, uint4* ee1f, uint4* ee2f, uint4* ec1f, uint4* cef)
{
    int i = blockIdx.x * blockDim.x + threadIdx.x;
    if (i < 2048) {
        prep_one(me_w1 + 128 * 128, w1cf, 16, 128, i);
    } else if (i < 4096) {
        prep_one(me_w2, w2f, 8, 64, i - 2048);
    } else if (i < 8192) {
        int j = i - 4096;
        int lane = j & 31, nt = (j >> 5) % 32, kc = j / (32 * 32);
        int k0 = kc * 16 + (lane & 3) * 2;
        int n = nt * 8 + (lane >> 2);
        int koff = (n < 128) ? 0 : 64;
        int nn = (n < 128) ? n : (n - 128);
        float v00 = me_w1[(koff + k0 + 0) * 128 + nn];
        float v01 = me_w1[(koff + k0 + 1) * 128 + nn];
        float v10 = me_w1[(koff + k0 + 8) * 128 + nn];
        float v11 = me_w1[(koff + k0 + 9) * 128 + nn];
        uint4 o;
        split2(v00, v01, o.x, o.z);
        split2(v10, v11, o.y, o.w);
        wcatf[j] = o;
    } else if (i < 10240) {
        prep_one(nu_w1, nuf, 8, 64, i - 8192);
    } else if (i < 11264) {
        prep_one(ne_w1, ne1f, 8, 64, i - 10240);
    } else if (i < 12288) {
        prep_one(ne_w2, ne2f, 8, 64, i - 11264);
    } else if (i < 13312) {
        prep_one(ee_w1, ee1f, 8, 64, i - 12288);
    } else if (i < 14336) {
        prep_one(ee_w2, ee2f, 8, 64, i - 13312);
    } else if (i < 15360) {
        prep_one(ec_w1, ec1f, 8, 64, i - 14336);
    } else if (i < 16384) {
        prep_one(ce_w, cef, 8, 64, i - 15360);
    }
}

// =====================================================================
// node encoder (+ fused UV): 64->64->64, then UV = nf@Wcat from regs
// =====================================================================
__global__ __launch_bounds__(256) void enc_mma_kernel(
    const float* __restrict__ X,
    const uint4* __restrict__ w1f, const float* __restrict__ b1,
    const uint4* __restrict__ w2f, const float* __restrict__ b2,
    float* __restrict__ Y,
    const uint4* __restrict__ wcatf, float* __restrict__ uv, int rows)
{
    __shared__ __half A_hi[128 * E_STRIDE];
    __shared__ __half A_lo[128 * E_STRIDE];
    __shared__ float b1s[64], b2s[64];

    const int tid = threadIdx.x, wid = tid >> 5, lane = tid & 31;
    const int r0 = blockIdx.x * 128;

    if (tid < 64) b1s[tid] = b1[tid];
    else if (tid < 128) b2s[tid - 64] = b2[tid - 64];

    stage_split64(X, r0, rows, A_hi, A_lo, tid);
    __syncthreads();

    const int m0 = wid * 16;
    const int lr = lane >> 2, lc = lane & 3;

    float d1[8][4];
    #pragma unroll
    for (int nt = 0; nt < 8; ++nt)
        #pragma unroll
        for (int j = 0; j < 4; ++j) d1[nt][j] = 0.f;

    #pragma unroll
    for (int kc = 0; kc < 4; ++kc) {
        unsigned ah[4], al[4];
        load_afrag(A_hi, A_lo, m0 + lr, kc * 16 + lc * 2, ah, al);
        #pragma unroll
        for (int nt = 0; nt < 8; ++nt) {
            uint4 w = w1f[(kc * 8 + nt) * 32 + lane];
            mma_f16(d1[nt], ah, w.x, w.y);
            mma_f16(d1[nt], al, w.x, w.y);
            mma_f16(d1[nt], ah, w.z, w.w);
        }
    }

    float d2[8][4];
    #pragma unroll
    for (int nt = 0; nt < 8; ++nt)
        #pragma unroll
        for (int j = 0; j < 4; ++j) d2[nt][j] = 0.f;

    #pragma unroll
    for (int kc = 0; kc < 4; ++kc) {
        float2 bia = *(float2*)&b1s[kc * 16 + lc * 2];
        float2 bib = *(float2*)&b1s[kc * 16 + 8 + lc * 2];
        float h00 = fmaxf(d1[2 * kc][0] + bia.x, 0.f);
        float h01 = fmaxf(d1[2 * kc][1] + bia.y, 0.f);
        float h10 = fmaxf(d1[2 * kc][2] + bia.x, 0.f);
        float h11 = fmaxf(d1[2 * kc][3] + bia.y, 0.f);
        float h20 = fmaxf(d1[2 * kc + 1][0] + bib.x, 0.f);
        float h21 = fmaxf(d1[2 * kc + 1][1] + bib.y, 0.f);
        float h30 = fmaxf(d1[2 * kc + 1][2] + bib.x, 0.f);
        float h31 = fmaxf(d1[2 * kc + 1][3] + bib.y, 0.f);
        unsigned ah[4], al[4];
        split2(h00, h01, ah[0], al[0]);
        split2(h10, h11, ah[1], al[1]);
        split2(h20, h21, ah[2], al[2]);
        split2(h30, h31, ah[3], al[3]);
        #pragma unroll
        for (int nt = 0; nt < 8; ++nt) {
            uint4 w = w2f[(kc * 8 + nt) * 32 + lane];
            mma_f16(d2[nt], ah, w.x, w.y);
            mma_f16(d2[nt], al, w.x, w.y);
            mma_f16(d2[nt], ah, w.z, w.w);
        }
    }

    int row0 = r0 + m0 + lr, row1 = row0 + 8;
    #pragma unroll
    for (int nt = 0; nt < 8; ++nt) {
        int col = nt * 8 + lc * 2;
        d2[nt][0] += b2s[col]; d2[nt][1] += b2s[col + 1];
        d2[nt][2] += b2s[col]; d2[nt][3] += b2s[col + 1];
        if (row0 < rows)
            *(float2*)(Y + (size_t)row0 * 64 + col) = make_float2(d2[nt][0], d2[nt][1]);
        if (row1 < rows)
            *(float2*)(Y + (size_t)row1 * 64 + col) = make_float2(d2[nt][2], d2[nt][3]);
    }

    // fused UV
    uv_from_regs(d2, wcatf, uv, row0, row1, lc, lane, rows);
}

// =====================================================================
// FUSED edge-encoder + msg step 1
// =====================================================================
__global__ __launch_bounds__(256) void encmsg_mma_kernel(
    const float* __restrict__ edge_attr, const float* __restrict__ uv,
    __half* __restrict__ efh, __half* __restrict__ efl,
    const int* __restrict__ src, const int* __restrict__ tgt,
    const uint4* __restrict__ ee1f, const float* __restrict__ eb1,
    const uint4* __restrict__ ee2f, const float* __restrict__ eb2,
    const uint4* __restrict__ w1cf, const float* __restrict__ mb1,
    const uint4* __restrict__ w2f, const float* __restrict__ mb2,
    float* __restrict__ aggr)
{
    __shared__ __half A_hi[128 * E_STRIDE];
    __shared__ __half A_lo[128 * E_STRIDE];
    __shared__ float eb1s[64], eb2s[64], mb2s[64];
    __shared__ float mb1s[128];

    const int tid = threadIdx.x, wid = tid >> 5, lane = tid & 31;
    const int e0 = blockIdx.x * 128;
    const int m0 = wid * 16;
    const int lr = lane >> 2, lc = lane & 3;
    const int row0 = m0 + lr, row1 = row0 + 8;
    const size_t g0 = (size_t)(e0 + row0) * 64;
    const size_t g1 = (size_t)(e0 + row1) * 64;

    const int sa0 = __ldg(src + e0 + row0), sa1 = __ldg(src + e0 + row1);
    const int tg0 = __ldg(tgt + e0 + row0), tg1 = __ldg(tgt + e0 + row1);

    float d1[16][4];
    {
        const float* up0 = uv + (size_t)sa0 * 256;
        const float* vp0 = uv + (size_t)tg0 * 256 + 128;
        const float* up1 = uv + (size_t)sa1 * 256;
        const float* vp1 = uv + (size_t)tg1 * 256 + 128;
        #pragma unroll
        for (int nt = 0; nt < 16; ++nt) {
            int c = nt * 8 + lc * 2;
            float2 a0 = *(const float2*)(up0 + c);
            float2 v0 = *(const float2*)(vp0 + c);
            float2 a1 = *(const float2*)(up1 + c);
            float2 v1 = *(const float2*)(vp1 + c);
            d1[nt][0] = a0.x + v0.x; d1[nt][1] = a0.y + v0.y;
            d1[nt][2] = a1.x + v1.x; d1[nt][3] = a1.y + v1.y;
        }
    }

    if (tid < 64) {
        eb1s[tid] = eb1[tid];
        eb2s[tid] = eb2[tid];
        mb2s[tid] = mb2[tid];
    } else if (tid < 192) {
        mb1s[tid - 64] = mb1[tid - 64];
    }

    stage_split64(edge_attr, e0, NE, A_hi, A_lo, tid);
    __syncthreads();

    float de1[8][4];
    #pragma unroll
    for (int nt = 0; nt < 8; ++nt)
        #pragma unroll
        for (int j = 0; j < 4; ++j) de1[nt][j] = 0.f;

    #pragma unroll
    for (int kc = 0; kc < 4; ++kc) {
        unsigned ah[4], al[4];
        load_afrag(A_hi, A_lo, row0, kc * 16 + lc * 2, ah, al);
        #pragma unroll
        for (int nt = 0; nt < 8; ++nt) {
            uint4 w = ee1f[(kc * 8 + nt) * 32 + lane];
            mma_f16(de1[nt], ah, w.x, w.y);
            mma_f16(de1[nt], al, w.x, w.y);
            mma_f16(de1[nt], ah, w.z, w.w);
        }
    }

    float de2[8][4];
    #pragma unroll
    for (int nt = 0; nt < 8; ++nt)
        #pragma unroll
        for (int j = 0; j < 4; ++j) de2[nt][j] = 0.f;

    #pragma unroll
    for (int kc = 0; kc < 4; ++kc) {
        float2 bia = *(float2*)&eb1s[kc * 16 + lc * 2];
        float2 bib = *(float2*)&eb1s[kc * 16 + 8 + lc * 2];
        float h00 = fmaxf(de1[2 * kc][0] + bia.x, 0.f);
        float h01 = fmaxf(de1[2 * kc][1] + bia.y, 0.f);
        float h10 = fmaxf(de1[2 * kc][2] + bia.x, 0.f);
        float h11 = fmaxf(de1[2 * kc][3] + bia.y, 0.f);
        float h20 = fmaxf(de1[2 * kc + 1][0] + bib.x, 0.f);
        float h21 = fmaxf(de1[2 * kc + 1][1] + bib.y, 0.f);
        float h30 = fmaxf(de1[2 * kc + 1][2] + bib.x, 0.f);
        float h31 = fmaxf(de1[2 * kc + 1][3] + bib.y, 0.f);
        unsigned ah[4], al[4];
        split2(h00, h01, ah[0], al[0]);
        split2(h10, h11, ah[1], al[1]);
        split2(h20, h21, ah[2], al[2]);
        split2(h30, h31, ah[3], al[3]);
        #pragma unroll
        for (int nt = 0; nt < 8; ++nt) {
            uint4 w = ee2f[(kc * 8 + nt) * 32 + lane];
            mma_f16(de2[nt], ah, w.x, w.y);
            mma_f16(de2[nt], al, w.x, w.y);
            mma_f16(de2[nt], ah, w.z, w.w);
        }
    }
    #pragma unroll
    for (int nt = 0; nt < 8; ++nt) {
        int col = nt * 8 + lc * 2;
        de2[nt][0] += eb2s[col]; de2[nt][1] += eb2s[col + 1];
        de2[nt][2] += eb2s[col]; de2[nt][3] += eb2s[col + 1];
    }

    #pragma unroll
    for (int kc = 0; kc < 4; ++kc) {
        unsigned ah[4], al[4];
        afrag_from_regs(de2[2 * kc], de2[2 * kc + 1], ah, al);
        #pragma unroll
        for (int nt = 0; nt < 16; ++nt) {
            uint4 w = w1cf[(kc * 16 + nt) * 32 + lane];
            mma_f16(d1[nt], ah, w.x, w.y);
            mma_f16(d1[nt], al, w.x, w.y);
            mma_f16(d1[nt], ah, w.z, w.w);
        }
    }

    float d2[8][4];
    #pragma unroll
    for (int nt = 0; nt < 8; ++nt)
        #pragma unroll
        for (int j = 0; j < 4; ++j) d2[nt][j] = 0.f;

    #pragma unroll
    for (int kc = 0; kc < 8; ++kc) {
        float2 bia = *(float2*)&mb1s[kc * 16 + lc * 2];
        float2 bib = *(float2*)&mb1s[kc * 16 + 8 + lc * 2];
        float h00 = fmaxf(d1[2 * kc][0] + bia.x, 0.f);
        float h01 = fmaxf(d1[2 * kc][1] + bia.y, 0.f);
        float h10 = fmaxf(d1[2 * kc][2] + bia.x, 0.f);
        float h11 = fmaxf(d1[2 * kc][3] + bia.y, 0.f);
        float h20 = fmaxf(d1[2 * kc + 1][0] + bib.x, 0.f);
        float h21 = fmaxf(d1[2 * kc + 1][1] + bib.y, 0.f);
        float h30 = fmaxf(d1[2 * kc + 1][2] + bib.x, 0.f);
        float h31 = fmaxf(d1[2 * kc + 1][3] + bib.y, 0.f);
        unsigned ah[4], al[4];
        split2(h00, h01, ah[0], al[0]);
        split2(h10, h11, ah[1], al[1]);
        split2(h20, h21, ah[2], al[2]);
        split2(h30, h31, ah[3], al[3]);
        #pragma unroll
        for (int nt = 0; nt < 8; ++nt) {
            uint4 w = w2f[(kc * 8 + nt) * 32 + lane];
            mma_f16(d2[nt], ah, w.x, w.y);
            mma_f16(d2[nt], al, w.x, w.y);
            mma_f16(d2[nt], ah, w.z, w.w);
        }
    }

    {
        float* ag0 = aggr + (size_t)tg0 * 64;
        float* ag1 = aggr + (size_t)tg1 * 64;
        #pragma unroll
        for (int nt = 0; nt < 8; ++nt) {
            int col = nt * 8 + lc * 2;
            float2 v0 = make_float2(d2[nt][0] + mb2s[col], d2[nt][1] + mb2s[col + 1]);
            float2 v1 = make_float2(d2[nt][2] + mb2s[col], d2[nt][3] + mb2s[col + 1]);
            unsigned hi0, lo0, hi1, lo1;
            split2(v0.x, v0.y, hi0, lo0);
            split2(v1.x, v1.y, hi1, lo1);
            *(unsigned*)(efh + g0 + col) = hi0;
            *(unsigned*)(efl + g0 + col) = lo0;
            *(unsigned*)(efh + g1 + col) = hi1;
            *(unsigned*)(efl + g1 + col) = lo1;
            atomicAdd((float2*)(ag0 + col), v0);
            atomicAdd((float2*)(ag1 + col), v1);
        }
    }
}

// =====================================================================
// msg (steps 2,3)
// =====================================================================
template <bool HEAD>
__global__ __launch_bounds__(256) void msg_mma_kernel(
    const float* __restrict__ uv,
    __half* __restrict__ efh, __half* __restrict__ efl,
    float* __restrict__ ef32,
    const int* __restrict__ src, const int* __restrict__ tgt,
    const uint4* __restrict__ w1cf, const float* __restrict__ b1,
    const uint4* __restrict__ w2f, const float* __restrict__ b2,
    float* __restrict__ aggr,
    const uint4* __restrict__ ec1f, const float* __restrict__ ec_b1,
    const float* __restrict__ ec_w2, const float* __restrict__ ec_b2,
    float* __restrict__ epred)
{
    __shared__ float b1s[128], b2s[64];
    __shared__ float ecb1s[64], ecw2s[64];

    const int tid = threadIdx.x, wid = tid >> 5, lane = tid & 31;
    const int e0 = blockIdx.x * 128;
    const int m0 = wid * 16;
    const int lr = lane >> 2, lc = lane & 3;
    const int row0 = m0 + lr, row1 = row0 + 8;
    const size_t g0 = (size_t)(e0 + row0) * 64;
    const size_t g1 = (size_t)(e0 + row1) * 64;

    const int sa0 = __ldg(src + e0 + row0), sa1 = __ldg(src + e0 + row1);
    const int tg0 = __ldg(tgt + e0 + row0), tg1 = __ldg(tgt + e0 + row1);

    float d1[16][4];
    {
        const float* up0 = uv + (size_t)sa0 * 256;
        const float* vp0 = uv + (size_t)tg0 * 256 + 128;
        const float* up1 = uv + (size_t)sa1 * 256;
        const float* vp1 = uv + (size_t)tg1 * 256 + 128;
        #pragma unroll
        for (int nt = 0; nt < 16; ++nt) {
            int c = nt * 8 + lc * 2;
            float2 a0 = *(const float2*)(up0 + c);
            float2 v0 = *(const float2*)(vp0 + c);
            float2 a1 = *(const float2*)(up1 + c);
            float2 v1 = *(const float2*)(vp1 + c);
            d1[nt][0] = a0.x + v0.x; d1[nt][1] = a0.y + v0.y;
            d1[nt][2] = a1.x + v1.x; d1[nt][3] = a1.y + v1.y;
        }
    }

    if (tid < 128) {
        b1s[tid] = b1[tid];
    } else if (tid < 192) {
        b2s[tid - 128] = b2[tid - 128];
    } else if (HEAD && tid < 256) {
        int t = tid - 192;
        ecb1s[t] = ec_b1[t];
        ecw2s[t] = ec_w2[t];
    }
    __syncthreads();

    #pragma unroll
    for (int kc = 0; kc < 4; ++kc) {
        int c0 = kc * 16 + lc * 2;
        unsigned ah[4], al[4];
        ah[0] = *(const unsigned*)(efh + g0 + c0);
        ah[1] = *(const unsigned*)(efh + g1 + c0);
        ah[2] = *(const unsigned*)(efh + g0 + c0 + 8);
        ah[3] = *(const unsigned*)(efh + g1 + c0 + 8);
        al[0] = *(const unsigned*)(efl + g0 + c0);
        al[1] = *(const unsigned*)(efl + g1 + c0);
        al[2] = *(const unsigned*)(efl + g0 + c0 + 8);
        al[3] = *(const unsigned*)(efl + g1 + c0 + 8);
        #pragma unroll
        for (int nt = 0; nt < 16; ++nt) {
            uint4 w = w1cf[(kc * 16 + nt) * 32 + lane];
            mma_f16(d1[nt], ah, w.x, w.y);
            mma_f16(d1[nt], al, w.x, w.y);
            mma_f16(d1[nt], ah, w.z, w.w);
        }
    }

    float d2[8][4];
    #pragma unroll
    for (int nt = 0; nt < 8; ++nt)
        #pragma unroll
        for (int j = 0; j < 4; ++j) d2[nt][j] = 0.f;

    #pragma unroll
    for (int kc = 0; kc < 8; ++kc) {
        float2 bia = *(float2*)&b1s[kc * 16 + lc * 2];
        float2 bib = *(float2*)&b1s[kc * 16 + 8 + lc * 2];
        float h00 = fmaxf(d1[2 * kc][0] + bia.x, 0.f);
        float h01 = fmaxf(d1[2 * kc][1] + bia.y, 0.f);
        float h10 = fmaxf(d1[2 * kc][2] + bia.x, 0.f);
        float h11 = fmaxf(d1[2 * kc][3] + bia.y, 0.f);
        float h20 = fmaxf(d1[2 * kc + 1][0] + bib.x, 0.f);
        float h21 = fmaxf(d1[2 * kc + 1][1] + bib.y, 0.f);
        float h30 = fmaxf(d1[2 * kc + 1][2] + bib.x, 0.f);
        float h31 = fmaxf(d1[2 * kc + 1][3] + bib.y, 0.f);
        unsigned ah[4], al[4];
        split2(h00, h01, ah[0], al[0]);
        split2(h10, h11, ah[1], al[1]);
        split2(h20, h21, ah[2], al[2]);
        split2(h30, h31, ah[3], al[3]);
        #pragma unroll
        for (int nt = 0; nt < 8; ++nt) {
            uint4 w = w2f[(kc * 8 + nt) * 32 + lane];
            mma_f16(d2[nt], ah, w.x, w.y);
            mma_f16(d2[nt], al, w.x, w.y);
            mma_f16(d2[nt], ah, w.z, w.w);
        }
    }

    {
        float* ag0 = aggr + (size_t)tg0 * 64;
        float* ag1 = aggr + (size_t)tg1 * 64;
        #pragma unroll
        for (int nt = 0; nt < 8; ++nt) {
            int col = nt * 8 + lc * 2;
            d2[nt][0] += b2s[col]; d2[nt][1] += b2s[col + 1];
            d2[nt][2] += b2s[col]; d2[nt][3] += b2s[col + 1];
            float2 v0 = make_float2(d2[nt][0], d2[nt][1]);
            float2 v1 = make_float2(d2[nt][2], d2[nt][3]);
            if (HEAD) {
                *(float2*)(ef32 + g0 + col) = v0;
                *(float2*)(ef32 + g1 + col) = v1;
            } else {
                unsigned hi0, lo0, hi1, lo1;
                split2(v0.x, v0.y, hi0, lo0);
                split2(v1.x, v1.y, hi1, lo1);
                *(unsigned*)(efh + g0 + col) = hi0;
                *(unsigned*)(efl + g0 + col) = lo0;
                *(unsigned*)(efh + g1 + col) = hi1;
                *(unsigned*)(efl + g1 + col) = lo1;
            }
            atomicAdd((float2*)(ag0 + col), v0);
            atomicAdd((float2*)(ag1 + col), v1);
        }
    }

    if (HEAD) {
        float dh[8][4];
        #pragma unroll
        for (int nt = 0; nt < 8; ++nt)
            #pragma unroll
            for (int j = 0; j < 4; ++j) dh[nt][j] = 0.f;

        #pragma unroll
        for (int kc = 0; kc < 4; ++kc) {
            unsigned ah[4], al[4];
            afrag_from_regs(d2[2 * kc], d2[2 * kc + 1], ah, al);
            #pragma unroll
            for (int nt = 0; nt < 8; ++nt) {
                uint4 w = ec1f[(kc * 8 + nt) * 32 + lane];
                mma_f16(dh[nt], ah, w.x, w.y);
                mma_f16(dh[nt], al, w.x, w.y);
                mma_f16(dh[nt], ah, w.z, w.w);
            }
        }

        float s0 = 0.f, s1 = 0.f;
        #pragma unroll
        for (int nt = 0; nt < 8; ++nt) {
            int col = nt * 8 + lc * 2;
            float w0 = ecw2s[col], w1v = ecw2s[col + 1];
            float bc0 = ecb1s[col], bc1 = ecb1s[col + 1];
            s0 += fmaxf(dh[nt][0] + bc0, 0.f) * w0 + fmaxf(dh[nt][1] + bc1, 0.f) * w1v;
            s1 += fmaxf(dh[nt][2] + bc0, 0.f) * w0 + fmaxf(dh[nt][3] + bc1, 0.f) * w1v;
        }
        s0 += __shfl_xor_sync(0xffffffffu, s0, 1);
        s0 += __shfl_xor_sync(0xffffffffu, s0, 2);
        s1 += __shfl_xor_sync(0xffffffffu, s1, 1);
        s1 += __shfl_xor_sync(0xffffffffu, s1, 2);
        if (lc == 0) {
            float bb = ec_b2[0];
            epred[e0 + row0] = s0 + bb;
            epred[e0 + row1] = s1 + bb;
        }
    }
}

// =====================================================================
// nu update (+ zero aggr; DO_UV: fused UV; LAST: mirror nf + fused emb)
// =====================================================================
template <bool DO_UV, bool LAST>
__global__ __launch_bounds__(256) void nu_mma_kernel(
    float* __restrict__ nf, float* __restrict__ aggr,
    const uint4* __restrict__ wf, const float* __restrict__ b,
    const uint4* __restrict__ wcatf, float* __restrict__ uv,
    float* __restrict__ nf_out,
    const uint4* __restrict__ cef, const float* __restrict__ ce_b,
    float* __restrict__ emb, int rows)
{
    __shared__ __half A_hi[128 * E_STRIDE];
    __shared__ __half A_lo[128 * E_STRIDE];
    __shared__ float bs[64], cebs[64];

    const int tid = threadIdx.x, wid = tid >> 5, lane = tid & 31;
    const int r0 = blockIdx.x * 128;
    if (tid < 64) bs[tid] = b[tid];
    else if (LAST && tid < 128) cebs[tid - 64] = ce_b[tid - 64];

    const int m0 = wid * 16;
    const int lr = lane >> 2, lc = lane & 3;

    float d[8][4];
    #pragma unroll
    for (int nt = 0; nt < 8; ++nt)
        #pragma unroll
        for (int j = 0; j < 4; ++j) d[nt][j] = 0.f;

    #pragma unroll
    for (int stage = 0; stage < 2; ++stage) {
        stage_split64(stage ? aggr : nf, r0, rows, A_hi, A_lo, tid);
        __syncthreads();
        #pragma unroll
        for (int kc = 0; kc < 4; ++kc) {
            unsigned ah[4], al[4];
            load_afrag(A_hi, A_lo, m0 + lr, kc * 16 + lc * 2, ah, al);
            #pragma unroll
            for (int nt = 0; nt < 8; ++nt) {
                uint4 w = wf[((stage * 4 + kc) * 8 + nt) * 32 + lane];
                mma_f16(d[nt], ah, w.x, w.y);
                mma_f16(d[nt], al, w.x, w.y);
                mma_f16(d[nt], ah, w.z, w.w);
            }
        }
        __syncthreads();
    }

    int row0 = r0 + m0 + lr, row1 = row0 + 8;
    #pragma unroll
    for (int nt = 0; nt < 8; ++nt) {
        int col = nt * 8 + lc * 2;
        d[nt][0] += bs[col]; d[nt][1] += bs[col + 1];
        d[nt][2] += bs[col]; d[nt][3] += bs[col + 1];
        if (row0 < rows) {
            *(float2*)(nf + (size_t)row0 * 64 + col) = make_float2(d[nt][0], d[nt][1]);
            if (LAST) *(float2*)(nf_out + (size_t)row0 * 64 + col) = make_float2(d[nt][0], d[nt][1]);
        }
        if (row1 < rows) {
            *(float2*)(nf + (size_t)row1 * 64 + col) = make_float2(d[nt][2], d[nt][3]);
            if (LAST) *(float2*)(nf_out + (size_t)row1 * 64 + col) = make_float2(d[nt][2], d[nt][3]);
        }
    }

    if (DO_UV) {
        uv_from_regs(d, wcatf, uv, row0, row1, lc, lane, rows);
    }

    if (LAST) {
        // emb = nf @ ce_w + ce_b (from regs)
        float de[8][4];
        #pragma unroll
        for (int nt = 0; nt < 8; ++nt)
            #pragma unroll
            for (int j = 0; j < 4; ++j) de[nt][j] = 0.f;
        #pragma unroll
        for (int kc = 0; kc < 4; ++kc) {
            unsigned ah[4], al[4];
            afrag_from_regs(d[2 * kc], d[2 * kc + 1], ah, al);
            #pragma unroll
            for (int nt = 0; nt < 8; ++nt) {
                uint4 w = cef[(kc * 8 + nt) * 32 + lane];
                mma_f16(de[nt], ah, w.x, w.y);
                mma_f16(de[nt], al, w.x, w.y);
                mma_f16(de[nt], ah, w.z, w.w);
            }
        }
        #pragma unroll
        for (int nt = 0; nt < 8; ++nt) {
            int col = nt * 8 + lc * 2;
            if (row0 < rows)
                *(float2*)(emb + (size_t)row0 * 64 + col) =
                    make_float2(de[nt][0] + cebs[col], de[nt][1] + cebs[col + 1]);
            if (row1 < rows)
                *(float2*)(emb + (size_t)row1 * 64 + col) =
                    make_float2(de[nt][2] + cebs[col], de[nt][3] + cebs[col + 1]);
        }
    } else {
        // zero aggr rows for the NEXT step (already consumed above)
        int r = r0 + (tid >> 1);
        if (r < rows) {
            float4* zp = (float4*)(aggr + (size_t)r * 64 + (tid & 1) * 32);
            #pragma unroll
            for (int j = 0; j < 8; ++j) zp[j] = make_float4(0.f, 0.f, 0.f, 0.f);
        }
    }
}

// =====================================================================
// node heads: 64 -> 64(relu) -> OUT, one warp per row
// =====================================================================
template <int OUT>
__global__ __launch_bounds__(256) void head_kernel(
    const float* __restrict__ X,
    const float* __restrict__ W1, const float* __restrict__ B1,
    const float* __restrict__ W2, const float* __restrict__ B2,
    float* __restrict__ Y, int* __restrict__ amax, int rows)
{
    __shared__ float sh[8][64];
    const int lane = threadIdx.x & 31, w = threadIdx.x >> 5;
    const int row = blockIdx.x * 8 + w;
    if (row >= rows) return;

    sh[w][lane]      = X[(size_t)row * 64 + lane];
    sh[w][lane + 32] = X[(size_t)row * 64 + lane + 32];
    __syncwarp();

    float h0 = B1[lane], h1 = B1[lane + 32];
    #pragma unroll
    for (int k = 0; k < 64; ++k) {
        float xv = sh[w][k];
        h0 = fmaf(xv, W1[k * 64 + lane], h0);
        h1 = fmaf(xv, W1[k * 64 + lane + 32], h1);
    }
    h0 = fmaxf(h0, 0.f); h1 = fmaxf(h1, 0.f);

    if (OUT == 1) {
        float s = h0 * W2[lane] + h1 * W2[lane + 32];
        #pragma unroll
        for (int off = 16; off; off >>= 1) s += __shfl_down_sync(0xffffffffu, s, off);
        if (lane == 0) Y[row] = s + B2[0];
    } else {
        __syncwarp();
        sh[w][lane] = h0; sh[w][lane + 32] = h1;
        __syncwarp();
        float bv = -INFINITY;
        int bi = 1 << 30;
        if (lane < OUT) {
            float val = B2[lane];
            #pragma unroll
            for (int k = 0; k < 64; ++k) val = fmaf(sh[w][k], W2[k * OUT + lane], val);
            Y[(size_t)row * OUT + lane] = val;
            bv = val; bi = lane;
        }
        #pragma unroll
        for (int off = 16; off; off >>= 1) {
            float ov = __shfl_down_sync(0xffffffffu, bv, off);
            int   oi = __shfl_down_sync(0xffffffffu, bi, off);
            if (ov > bv || (ov == bv && oi < bi)) { bv = ov; bi = oi; }
        }
        if (lane == 0 && amax) amax[row] = bi;
    }
}

// =====================================================================
// type-constrained scatter softmax pieces
// =====================================================================
__global__ void init_softmax_kernel(unsigned* mx, float* denom, int n) {
    int i = blockIdx.x * blockDim.x + threadIdx.x;
    if (i < n) { mx[i] = 0u; denom[i] = 0.f; }
}

__global__ __launch_bounds__(256) void scores_kernel(
    const float* __restrict__ emb, const int* __restrict__ src, const int* __restrict__ tgt,
    const int* __restrict__ types, float* __restrict__ scores, int* __restrict__ seg,
    unsigned* __restrict__ mx)
{
    const int lane = threadIdx.x & 31, w = threadIdx.x >> 5;
    const int e = blockIdx.x * 8 + w;
    if (e >= NE) return;
    int s = src[e], t = tgt[e];
    const float* es = emb + (size_t)s * 64;
    const float* et = emb + (size_t)t * 64;
    float p = es[lane] * et[lane] + es[lane + 32] * et[lane + 32];
    #pragma unroll
    for (int off = 16; off; off >>= 1) p += __shfl_down_sync(0xffffffffu, p, off);
    if (lane == 0) {
        scores[e] = p;
        int sg = t * NT + types[s];
        seg[e] = sg;
        atomicMax(&mx[sg], ordf(p));
    }
}

__global__ void ex_kernel(float* __restrict__ scores, const int* __restrict__ seg,
                          const unsigned* __restrict__ mx, float* __restrict__ denom, int n) {
    int i = blockIdx.x * blockDim.x + threadIdx.x;
    if (i < n) {
        int sg = seg[i];
        float exv = expf(scores[i] - deord(mx[sg]));
        scores[i] = exv;
        atomicAdd(&denom[sg], exv);
    }
}

__global__ void final_kernel(const float* __restrict__ ex, const int* __restrict__ seg,
                             const float* __restrict__ denom, const float* __restrict__ epred,
                             float* __restrict__ out_edge, int n) {
    int i = blockIdx.x * blockDim.x + threadIdx.x;
    if (i < n) {
        float sig = 1.f / (1.f + expf(-epred[i]));
        out_edge[i] = ex[i] / denom[seg[i]] * sig;
    }
}

__global__ void zero_kernel(float* p, int n) {
    int i = blockIdx.x * blockDim.x + threadIdx.x;
    if (i < n) p[i] = 0.f;
}

// =====================================================================
// launch
// =====================================================================
extern "C" void kernel_launch(void* const* d_in, const int* in_sizes, int n_in,
                              void* d_out, int out_size)
{
    const float* x         = (const float*)d_in[0];
    const float* edge_attr = (const float*)d_in[1];
    const int*   eidx      = (const int*)d_in[2];
    const int*   src = eidx;
    const int*   tgt = eidx + NE;
    const float *ne_w1 = (const float*)d_in[4],  *ne_b1 = (const float*)d_in[5];
    const float *ne_w2 = (const float*)d_in[6],  *ne_b2 = (const float*)d_in[7];
    const float *ee_w1 = (const float*)d_in[8],  *ee_b1 = (const float*)d_in[9];
    const float *ee_w2 = (const float*)d_in[10], *ee_b2 = (const float*)d_in[11];
    const float *me_w1 = (const float*)d_in[12], *me_b1 = (const float*)d_in[13];
    const float *me_w2 = (const float*)d_in[14], *me_b2 = (const float*)d_in[15];
    const float *nu_w1 = (const float*)d_in[16], *nu_b1 = (const float*)d_in[17];
    const float *ec_w1 = (const float*)d_in[18], *ec_b1 = (const float*)d_in[19];
    const float *ec_w2 = (const float*)d_in[20], *ec_b2 = (const float*)d_in[21];
    const float *nc_w1 = (const float*)d_in[22], *nc_b1 = (const float*)d_in[23];
    const float *nc_w2 = (const float*)d_in[24], *nc_b2 = (const float*)d_in[25];
    const float *cl_w1 = (const float*)d_in[26], *cl_b1 = (const float*)d_in[27];
    const float *cl_w2 = (const float*)d_in[28], *cl_b2 = (const float*)d_in[29];
    const float *ce_w  = (const float*)d_in[30], *ce_b  = (const float*)d_in[31];

    float* out = (float*)d_out;
    float* out_edge = out;
    float* out_node = out + NE;
    float* out_cls  = out_node + NN;
    float* out_nf   = out_cls + (size_t)NN * NT;
    float* out_ef   = out_nf + (size_t)NN * 64;

    float *p_nf, *p_aggr, *p_uv, *p_emb, *p_scores, *p_denom, *p_epred;
    __half *p_efh, *p_efl;
    int *p_seg, *p_types;
    unsigned* p_mx;
    uint4 *p_w1cf, *p_w2f, *p_wcatf, *p_nuf, *p_ne1f, *p_ne2f, *p_ee1f, *p_ee2f, *p_ec1f, *p_cef;
    cudaGetSymbolAddress((void**)&p_nf, g_nf);
    cudaGetSymbolAddress((void**)&p_aggr, g_aggr);
    cudaGetSymbolAddress((void**)&p_uv, g_uv);
    cudaGetSymbolAddress((void**)&p_efh, g_efh);
    cudaGetSymbolAddress((void**)&p_efl, g_efl);
    cudaGetSymbolAddress((void**)&p_emb, g_emb);
    cudaGetSymbolAddress((void**)&p_scores, g_scores);
    cudaGetSymbolAddress((void**)&p_seg, g_seg);
    cudaGetSymbolAddress((void**)&p_epred, g_epred);
    cudaGetSymbolAddress((void**)&p_mx, g_mx);
    cudaGetSymbolAddress((void**)&p_denom, g_denom);
    cudaGetSymbolAddress((void**)&p_types, g_types);
    cudaGetSymbolAddress((void**)&p_w1cf, g_w1cf);
    cudaGetSymbolAddress((void**)&p_w2f, g_w2f);
    cudaGetSymbolAddress((void**)&p_wcatf, g_wcatf);
    cudaGetSymbolAddress((void**)&p_nuf, g_nuf);
    cudaGetSymbolAddress((void**)&p_ne1f, g_ne1f);
    cudaGetSymbolAddress((void**)&p_ne2f, g_ne2f);
    cudaGetSymbolAddress((void**)&p_ee1f, g_ee1f);
    cudaGetSymbolAddress((void**)&p_ee2f, g_ee2f);
    cudaGetSymbolAddress((void**)&p_ec1f, g_ec1f);
    cudaGetSymbolAddress((void**)&p_cef, g_cef);

    // 1: all weight prep in one launch (64 blocks covers 16384 items)
    prep_all_kernel<<<64, 256>>>(me_w1, me_w2, nu_w1, ne_w1, ne_w2, ee_w1, ee_w2, ec_w1, ce_w,
                                 p_w1cf, p_w2f, p_wcatf, p_nuf,
                                 p_ne1f, p_ne2f, p_ee1f, p_ee2f, p_ec1f, p_cef);

    // 2: node encoder (+ fused UV for step 1)
    enc_mma_kernel<<<(NN + 127) / 128, 256>>>(x, p_ne1f, ne_b1, p_ne2f, ne_b2, p_nf,
                                              p_wcatf, p_uv, NN);

    // 3: zero aggr once (subsequent zeroing fused into nu)
    zero_kernel<<<(NN * 64 + 255) / 256, 256>>>(p_aggr, NN * 64);

    // step 1: FUSED edge-encoder+msg + nu(+uv)
    encmsg_mma_kernel<<<NE / 128, 256>>>(edge_attr, p_uv, p_efh, p_efl, src, tgt,
                                         p_ee1f, ee_b1, p_ee2f, ee_b2,
                                         p_w1cf, me_b1, p_w2f, me_b2, p_aggr);
    nu_mma_kernel<true, false><<<(NN + 127) / 128, 256>>>(p_nf, p_aggr, p_nuf, nu_b1,
                                                          p_wcatf, p_uv, nullptr,
                                                          nullptr, nullptr, nullptr, NN);

    // step 2
    msg_mma_kernel<false><<<NE / 128, 256>>>(p_uv, p_efh, p_efl, nullptr, src, tgt,
                                             p_w1cf, me_b1, p_w2f, me_b2, p_aggr,
                                             nullptr, nullptr, nullptr, nullptr, nullptr);
    nu_mma_kernel<true, false><<<(NN + 127) / 128, 256>>>(p_nf, p_aggr, p_nuf, nu_b1,
                                                          p_wcatf, p_uv, nullptr,
                                                          nullptr, nullptr, nullptr, NN);

    // step 3 (HEAD fused; last nu mirrors nf + computes emb)
    msg_mma_kernel<true><<<NE / 128, 256>>>(p_uv, p_efh, p_efl, out_ef, src, tgt,
                                            p_w1cf, me_b1, p_w2f, me_b2, p_aggr,
                                            p_ec1f, ec_b1, ec_w2, ec_b2, p_epred);
    nu_mma_kernel<false, true><<<(NN + 127) / 128, 256>>>(p_nf, p_aggr, p_nuf, nu_b1,
                                                          nullptr, nullptr, out_nf,
                                                          p_cef, ce_b, p_emb, NN);

    // node heads
    head_kernel<1><<<(NN + 7) / 8, 256>>>(p_nf, nc_w1, nc_b1, nc_w2, nc_b2, out_node, nullptr, NN);
    head_kernel<NT><<<(NN + 7) / 8, 256>>>(p_nf, cl_w1, cl_b1, cl_w2, cl_b2, out_cls, p_types, NN);

    // type-constrained scatter softmax
    init_softmax_kernel<<<(NN * NT + 255) / 256, 256>>>(p_mx, p_denom, NN * NT);
    scores_kernel<<<(NE + 7) / 8, 256>>>(p_emb, src, tgt, p_types, p_scores, p_seg, p_mx);
    ex_kernel<<<(NE + 255) / 256, 256>>>(p_scores, p_seg, p_mx, p_denom, NE);
    final_kernel<<<(NE + 255) / 256, 256>>>(p_scores, p_seg, p_denom, p_epred, out_edge, NE);
}

// round 15
// speedup vs baseline: 1.5455x; 1.5455x over previous
#include <cuda_runtime.h>
#include <cuda_fp16.h>
#include <math.h>
#include <stdint.h>

#define NN 50000
#define NE 800000
#define NT 17

// ---------------- scratch ----------------
__device__ float    g_nf[NN * 64];
__device__ float    g_aggr[NN * 64];
__device__ float    g_uv[(size_t)NN * 256];
__device__ __half   g_efh[(size_t)NE * 64];
__device__ __half   g_efl[(size_t)NE * 64];
__device__ float    g_emb[NN * 64];
__device__ float    g_scores[NE];
__device__ int      g_seg[NE];
__device__ float    g_epred[NE];
__device__ unsigned g_mx[NN * NT];
__device__ float    g_denom[NN * NT];
__device__ int      g_types[NN];
__device__ uint4    g_w1cf[4 * 16 * 32];
__device__ uint4    g_w2f[8 * 8 * 32];
__device__ uint4    g_wcatf[4 * 32 * 32];
__device__ uint4    g_nuf[8 * 8 * 32];
__device__ uint4    g_ne1f[4 * 8 * 32];
__device__ uint4    g_ne2f[4 * 8 * 32];
__device__ uint4    g_ee1f[4 * 8 * 32];
__device__ uint4    g_ee2f[4 * 8 * 32];
__device__ uint4    g_ec1f[4 * 8 * 32];

__device__ __forceinline__ unsigned ordf(float f) {
    unsigned u = __float_as_uint(f);
    return (u & 0x80000000u) ? ~u : (u | 0x80000000u);
}
__device__ __forceinline__ float deord(unsigned u) {
    return (u & 0x80000000u) ? __uint_as_float(u ^ 0x80000000u) : __uint_as_float(~u);
}

__device__ __forceinline__ unsigned pk(__half a, __half b) {
    return (unsigned)__half_as_ushort(a) | ((unsigned)__half_as_ushort(b) << 16);
}
__device__ __forceinline__ void split2(float x, float y, unsigned& hi, unsigned& lo) {
    __half hx = __float2half_rn(x), hy = __float2half_rn(y);
    float rx = x - __half2float(hx), ry = y - __half2float(hy);
    hi = pk(hx, hy);
    lo = pk(__float2half_rn(rx), __float2half_rn(ry));
}

__device__ __forceinline__ void mma_f16(float* d, const unsigned* a, unsigned b0, unsigned b1) {
    asm volatile(
        "mma.sync.aligned.m16n8k16.row.col.f32.f16.f16.f32 "
        "{%0,%1,%2,%3}, {%4,%5,%6,%7}, {%8,%9}, {%0,%1,%2,%3};"
        : "+f"(d[0]), "+f"(d[1]), "+f"(d[2]), "+f"(d[3])
        : "r"(a[0]), "r"(a[1]), "r"(a[2]), "r"(a[3]), "r"(b0), "r"(b1));
}

#define E_STRIDE 72

__device__ __forceinline__ void load_afrag(const __half* A_hi, const __half* A_lo,
                                           int row0, int k0, unsigned* ah, unsigned* al) {
    ah[0] = *(const unsigned*)(A_hi + row0 * E_STRIDE + k0);
    ah[1] = *(const unsigned*)(A_hi + (row0 + 8) * E_STRIDE + k0);
    ah[2] = *(const unsigned*)(A_hi + row0 * E_STRIDE + k0 + 8);
    ah[3] = *(const unsigned*)(A_hi + (row0 + 8) * E_STRIDE + k0 + 8);
    al[0] = *(const unsigned*)(A_lo + row0 * E_STRIDE + k0);
    al[1] = *(const unsigned*)(A_lo + (row0 + 8) * E_STRIDE + k0);
    al[2] = *(const unsigned*)(A_lo + row0 * E_STRIDE + k0 + 8);
    al[3] = *(const unsigned*)(A_lo + (row0 + 8) * E_STRIDE + k0 + 8);
}

__device__ __forceinline__ void stage_split64(const float* __restrict__ X, int r0, int rows,
                                              __half* A_hi, __half* A_lo, int tid) {
    const int r = tid >> 1, h = tid & 1;
    int gr = min(r0 + r, rows - 1);
    const float* rowp = X + (size_t)gr * 64 + h * 32;
    #pragma unroll
    for (int j = 0; j < 8; ++j) {
        float4 v = *(const float4*)(rowp + j * 4);
        int col = h * 32 + j * 4;
        unsigned h0, l0, h1, l1;
        split2(v.x, v.y, h0, l0);
        split2(v.z, v.w, h1, l1);
        *(uint2*)(A_hi + r * E_STRIDE + col) = make_uint2(h0, h1);
        *(uint2*)(A_lo + r * E_STRIDE + col) = make_uint2(l0, l1);
    }
}

__device__ __forceinline__ void afrag_from_regs(const float df0[4], const float df1[4],
                                                unsigned* ah, unsigned* al) {
    split2(df0[0], df0[1], ah[0], al[0]);
    split2(df0[2], df0[3], ah[1], al[1]);
    split2(df1[0], df1[1], ah[2], al[2]);
    split2(df1[2], df1[3], ah[3], al[3]);
}

// =====================================================================
// Weight prep (single fused launch)
// =====================================================================
__device__ __forceinline__ void prep_one(const float* __restrict__ W, uint4* __restrict__ out,
                                         int NTILES, int Ncols, int i) {
    int lane = i & 31, nt = (i >> 5) % NTILES, kc = i / (32 * NTILES);
    int k0 = kc * 16 + (lane & 3) * 2;
    int n = nt * 8 + (lane >> 2);
    float v00 = W[(k0 + 0) * Ncols + n];
    float v01 = W[(k0 + 1) * Ncols + n];
    float v10 = W[(k0 + 8) * Ncols + n];
    float v11 = W[(k0 + 9) * Ncols + n];
    uint4 o;
    split2(v00, v01, o.x, o.z);
    split2(v10, v11, o.y, o.w);
    out[i] = o;
}

__global__ void prep_all_kernel(
    const float* me_w1, const float* me_w2, const float* nu_w1,
    const float* ne_w1, const float* ne_w2, const float* ee_w1,
    const float* ee_w2, const float* ec_w1,
    uint4* w1cf, uint4* w2f, uint4* wcatf, uint4* nuf,
    uint4* ne1f, uint4* ne2f, uint4* ee1f, uint4* ee2f, uint4* ec1f)
{
    int i = blockIdx.x * blockDim.x + threadIdx.x;
    if (i < 2048) {
        prep_one(me_w1 + 128 * 128, w1cf, 16, 128, i);
    } else if (i < 4096) {
        prep_one(me_w2, w2f, 8, 64, i - 2048);
    } else if (i < 8192) {
        int j = i - 4096;
        int lane = j & 31, nt = (j >> 5) % 32, kc = j / (32 * 32);
        int k0 = kc * 16 + (lane & 3) * 2;
        int n = nt * 8 + (lane >> 2);
        int koff = (n < 128) ? 0 : 64;
        int nn = (n < 128) ? n : (n - 128);
        float v00 = me_w1[(koff + k0 + 0) * 128 + nn];
        float v01 = me_w1[(koff + k0 + 1) * 128 + nn];
        float v10 = me_w1[(koff + k0 + 8) * 128 + nn];
        float v11 = me_w1[(koff + k0 + 9) * 128 + nn];
        uint4 o;
        split2(v00, v01, o.x, o.z);
        split2(v10, v11, o.y, o.w);
        wcatf[j] = o;
    } else if (i < 10240) {
        prep_one(nu_w1, nuf, 8, 64, i - 8192);
    } else if (i < 11264) {
        prep_one(ne_w1, ne1f, 8, 64, i - 10240);
    } else if (i < 12288) {
        prep_one(ne_w2, ne2f, 8, 64, i - 11264);
    } else if (i < 13312) {
        prep_one(ee_w1, ee1f, 8, 64, i - 12288);
    } else if (i < 14336) {
        prep_one(ee_w2, ee2f, 8, 64, i - 13312);
    } else if (i < 15360) {
        prep_one(ec_w1, ec1f, 8, 64, i - 14336);
    }
}

// =====================================================================
// UV precompute
// =====================================================================
__global__ __launch_bounds__(256) void uv_mma_kernel(
    const float* __restrict__ nf, const uint4* __restrict__ wcatf,
    float* __restrict__ uv, int rows)
{
    __shared__ __half A_hi[128 * E_STRIDE];
    __shared__ __half A_lo[128 * E_STRIDE];
    const int tid = threadIdx.x, wid = tid >> 5, lane = tid & 31;
    const int r0 = blockIdx.x * 128;
    const int ntb = blockIdx.y * 16;

    stage_split64(nf, r0, rows, A_hi, A_lo, tid);
    __syncthreads();

    const int m0 = wid * 16;
    const int lr = lane >> 2, lc = lane & 3;

    float d[16][4];
    #pragma unroll
    for (int nt = 0; nt < 16; ++nt)
        #pragma unroll
        for (int j = 0; j < 4; ++j) d[nt][j] = 0.f;

    #pragma unroll
    for (int kc = 0; kc < 4; ++kc) {
        unsigned ah[4], al[4];
        load_afrag(A_hi, A_lo, m0 + lr, kc * 16 + lc * 2, ah, al);
        #pragma unroll
        for (int nt = 0; nt < 16; ++nt) {
            uint4 w = wcatf[(kc * 32 + ntb + nt) * 32 + lane];
            mma_f16(d[nt], ah, w.x, w.y);
            mma_f16(d[nt], al, w.x, w.y);
            mma_f16(d[nt], ah, w.z, w.w);
        }
    }

    int row0 = r0 + m0 + lr, row1 = row0 + 8;
    int cb = blockIdx.y * 128;
    #pragma unroll
    for (int nt = 0; nt < 16; ++nt) {
        int col = cb + nt * 8 + lc * 2;
        if (row0 < rows) *(float2*)(uv + (size_t)row0 * 256 + col) = make_float2(d[nt][0], d[nt][1]);
        if (row1 < rows) *(float2*)(uv + (size_t)row1 * 256 + col) = make_float2(d[nt][2], d[nt][3]);
    }
}

// =====================================================================
// FUSED edge-encoder + msg step 1 (R13 form)
// =====================================================================
__global__ __launch_bounds__(256) void encmsg_mma_kernel(
    const float* __restrict__ edge_attr, const float* __restrict__ uv,
    __half* __restrict__ efh, __half* __restrict__ efl,
    const int* __restrict__ src, const int* __restrict__ tgt,
    const uint4* __restrict__ ee1f, const float* __restrict__ eb1,
    const uint4* __restrict__ ee2f, const float* __restrict__ eb2,
    const uint4* __restrict__ w1cf, const float* __restrict__ mb1,
    const uint4* __restrict__ w2f, const float* __restrict__ mb2,
    float* __restrict__ aggr)
{
    __shared__ __half A_hi[128 * E_STRIDE];
    __shared__ __half A_lo[128 * E_STRIDE];
    __shared__ float eb1s[64], eb2s[64], mb2s[64];
    __shared__ float mb1s[128];

    const int tid = threadIdx.x, wid = tid >> 5, lane = tid & 31;
    const int e0 = blockIdx.x * 128;
    const int m0 = wid * 16;
    const int lr = lane >> 2, lc = lane & 3;
    const int row0 = m0 + lr, row1 = row0 + 8;
    const size_t g0 = (size_t)(e0 + row0) * 64;
    const size_t g1 = (size_t)(e0 + row1) * 64;

    const int sa0 = __ldg(src + e0 + row0), sa1 = __ldg(src + e0 + row1);
    const int tg0 = __ldg(tgt + e0 + row0), tg1 = __ldg(tgt + e0 + row1);

    float d1[16][4];
    {
        const float* up0 = uv + (size_t)sa0 * 256;
        const float* vp0 = uv + (size_t)tg0 * 256 + 128;
        const float* up1 = uv + (size_t)sa1 * 256;
        const float* vp1 = uv + (size_t)tg1 * 256 + 128;
        #pragma unroll
        for (int nt = 0; nt < 16; ++nt) {
            int c = nt * 8 + lc * 2;
            float2 a0 = *(const float2*)(up0 + c);
            float2 v0 = *(const float2*)(vp0 + c);
            float2 a1 = *(const float2*)(up1 + c);
            float2 v1 = *(const float2*)(vp1 + c);
            d1[nt][0] = a0.x + v0.x; d1[nt][1] = a0.y + v0.y;
            d1[nt][2] = a1.x + v1.x; d1[nt][3] = a1.y + v1.y;
        }
    }

    if (tid < 64) {
        eb1s[tid] = eb1[tid];
        eb2s[tid] = eb2[tid];
        mb2s[tid] = mb2[tid];
    } else if (tid < 192) {
        mb1s[tid - 64] = mb1[tid - 64];
    }

    stage_split64(edge_attr, e0, NE, A_hi, A_lo, tid);
    __syncthreads();

    float de1[8][4];
    #pragma unroll
    for (int nt = 0; nt < 8; ++nt)
        #pragma unroll
        for (int j = 0; j < 4; ++j) de1[nt][j] = 0.f;

    #pragma unroll
    for (int kc = 0; kc < 4; ++kc) {
        unsigned ah[4], al[4];
        load_afrag(A_hi, A_lo, row0, kc * 16 + lc * 2, ah, al);
        #pragma unroll
        for (int nt = 0; nt < 8; ++nt) {
            uint4 w = ee1f[(kc * 8 + nt) * 32 + lane];
            mma_f16(de1[nt], ah, w.x, w.y);
            mma_f16(de1[nt], al, w.x, w.y);
            mma_f16(de1[nt], ah, w.z, w.w);
        }
    }

    float de2[8][4];
    #pragma unroll
    for (int nt = 0; nt < 8; ++nt)
        #pragma unroll
        for (int j = 0; j < 4; ++j) de2[nt][j] = 0.f;

    #pragma unroll
    for (int kc = 0; kc < 4; ++kc) {
        float2 bia = *(float2*)&eb1s[kc * 16 + lc * 2];
        float2 bib = *(float2*)&eb1s[kc * 16 + 8 + lc * 2];
        float h00 = fmaxf(de1[2 * kc][0] + bia.x, 0.f);
        float h01 = fmaxf(de1[2 * kc][1] + bia.y, 0.f);
        float h10 = fmaxf(de1[2 * kc][2] + bia.x, 0.f);
        float h11 = fmaxf(de1[2 * kc][3] + bia.y, 0.f);
        float h20 = fmaxf(de1[2 * kc + 1][0] + bib.x, 0.f);
        float h21 = fmaxf(de1[2 * kc + 1][1] + bib.y, 0.f);
        float h30 = fmaxf(de1[2 * kc + 1][2] + bib.x, 0.f);
        float h31 = fmaxf(de1[2 * kc + 1][3] + bib.y, 0.f);
        unsigned ah[4], al[4];
        split2(h00, h01, ah[0], al[0]);
        split2(h10, h11, ah[1], al[1]);
        split2(h20, h21, ah[2], al[2]);
        split2(h30, h31, ah[3], al[3]);
        #pragma unroll
        for (int nt = 0; nt < 8; ++nt) {
            uint4 w = ee2f[(kc * 8 + nt) * 32 + lane];
            mma_f16(de2[nt], ah, w.x, w.y);
            mma_f16(de2[nt], al, w.x, w.y);
            mma_f16(de2[nt], ah, w.z, w.w);
        }
    }
    #pragma unroll
    for (int nt = 0; nt < 8; ++nt) {
        int col = nt * 8 + lc * 2;
        de2[nt][0] += eb2s[col]; de2[nt][1] += eb2s[col + 1];
        de2[nt][2] += eb2s[col]; de2[nt][3] += eb2s[col + 1];
    }

    #pragma unroll
    for (int kc = 0; kc < 4; ++kc) {
        unsigned ah[4], al[4];
        afrag_from_regs(de2[2 * kc], de2[2 * kc + 1], ah, al);
        #pragma unroll
        for (int nt = 0; nt < 16; ++nt) {
            uint4 w = w1cf[(kc * 16 + nt) * 32 + lane];
            mma_f16(d1[nt], ah, w.x, w.y);
            mma_f16(d1[nt], al, w.x, w.y);
            mma_f16(d1[nt], ah, w.z, w.w);
        }
    }

    float d2[8][4];
    #pragma unroll
    for (int nt = 0; nt < 8; ++nt)
        #pragma unroll
        for (int j = 0; j < 4; ++j) d2[nt][j] = 0.f;

    #pragma unroll
    for (int kc = 0; kc < 8; ++kc) {
        float2 bia = *(float2*)&mb1s[kc * 16 + lc * 2];
        float2 bib = *(float2*)&mb1s[kc * 16 + 8 + lc * 2];
        float h00 = fmaxf(d1[2 * kc][0] + bia.x, 0.f);
        float h01 = fmaxf(d1[2 * kc][1] + bia.y, 0.f);
        float h10 = fmaxf(d1[2 * kc][2] + bia.x, 0.f);
        float h11 = fmaxf(d1[2 * kc][3] + bia.y, 0.f);
        float h20 = fmaxf(d1[2 * kc + 1][0] + bib.x, 0.f);
        float h21 = fmaxf(d1[2 * kc + 1][1] + bib.y, 0.f);
        float h30 = fmaxf(d1[2 * kc + 1][2] + bib.x, 0.f);
        float h31 = fmaxf(d1[2 * kc + 1][3] + bib.y, 0.f);
        unsigned ah[4], al[4];
        split2(h00, h01, ah[0], al[0]);
        split2(h10, h11, ah[1], al[1]);
        split2(h20, h21, ah[2], al[2]);
        split2(h30, h31, ah[3], al[3]);
        #pragma unroll
        for (int nt = 0; nt < 8; ++nt) {
            uint4 w = w2f[(kc * 8 + nt) * 32 + lane];
            mma_f16(d2[nt], ah, w.x, w.y);
            mma_f16(d2[nt], al, w.x, w.y);
            mma_f16(d2[nt], ah, w.z, w.w);
        }
    }

    {
        float* ag0 = aggr + (size_t)tg0 * 64;
        float* ag1 = aggr + (size_t)tg1 * 64;
        #pragma unroll
        for (int nt = 0; nt < 8; ++nt) {
            int col = nt * 8 + lc * 2;
            float2 v0 = make_float2(d2[nt][0] + mb2s[col], d2[nt][1] + mb2s[col + 1]);
            float2 v1 = make_float2(d2[nt][2] + mb2s[col], d2[nt][3] + mb2s[col + 1]);
            unsigned hi0, lo0, hi1, lo1;
            split2(v0.x, v0.y, hi0, lo0);
            split2(v1.x, v1.y, hi1, lo1);
            *(unsigned*)(efh + g0 + col) = hi0;
            *(unsigned*)(efl + g0 + col) = lo0;
            *(unsigned*)(efh + g1 + col) = hi1;
            *(unsigned*)(efl + g1 + col) = lo1;
            atomicAdd((float2*)(ag0 + col), v0);
            atomicAdd((float2*)(ag1 + col), v1);
        }
    }
}

// =====================================================================
// msg v3 (steps 2,3): interleaved layer1/layer2 per hidden chunk.
// ef A-frags cached in regs; UV loads software-pipelined.
// 2 CTAs/SM via __launch_bounds__(256,2).
// =====================================================================
template <bool HEAD>
__global__ void __launch_bounds__(256, 2) msg_mma_kernel(
    const float* __restrict__ uv,
    __half* __restrict__ efh, __half* __restrict__ efl,
    float* __restrict__ ef32,
    const int* __restrict__ src, const int* __restrict__ tgt,
    const uint4* __restrict__ w1cf, const float* __restrict__ b1,
    const uint4* __restrict__ w2f, const float* __restrict__ b2,
    float* __restrict__ aggr,
    const uint4* __restrict__ ec1f, const float* __restrict__ ec_b1,
    const float* __restrict__ ec_w2, const float* __restrict__ ec_b2,
    float* __restrict__ epred)
{
    __shared__ float b1s[128], b2s[64];
    __shared__ float ecb1s[64], ecw2s[64];

    const int tid = threadIdx.x, wid = tid >> 5, lane = tid & 31;
    const int e0 = blockIdx.x * 128;
    const int m0 = wid * 16;
    const int lr = lane >> 2, lc = lane & 3;
    const int row0 = m0 + lr, row1 = row0 + 8;
    const size_t g0 = (size_t)(e0 + row0) * 64;
    const size_t g1 = (size_t)(e0 + row1) * 64;

    const int sa0 = __ldg(src + e0 + row0), sa1 = __ldg(src + e0 + row1);
    const int tg0 = __ldg(tgt + e0 + row0), tg1 = __ldg(tgt + e0 + row1);

    const float* up0 = uv + (size_t)sa0 * 256;
    const float* vp0 = uv + (size_t)tg0 * 256 + 128;
    const float* up1 = uv + (size_t)sa1 * 256;
    const float* vp1 = uv + (size_t)tg1 * 256 + 128;

    // ef layer-1 A-frags (all 4 K-chunks) in regs
    unsigned efah[4][4], efal[4][4];
    #pragma unroll
    for (int kc = 0; kc < 4; ++kc) {
        int c0 = kc * 16 + lc * 2;
        efah[kc][0] = *(const unsigned*)(efh + g0 + c0);
        efah[kc][1] = *(const unsigned*)(efh + g1 + c0);
        efah[kc][2] = *(const unsigned*)(efh + g0 + c0 + 8);
        efah[kc][3] = *(const unsigned*)(efh + g1 + c0 + 8);
        efal[kc][0] = *(const unsigned*)(efl + g0 + c0);
        efal[kc][1] = *(const unsigned*)(efl + g1 + c0);
        efal[kc][2] = *(const unsigned*)(efl + g0 + c0 + 8);
        efal[kc][3] = *(const unsigned*)(efl + g1 + c0 + 8);
    }

    if (tid < 128) {
        b1s[tid] = b1[tid];
    } else if (tid < 192) {
        b2s[tid - 128] = b2[tid - 128];
    } else if (HEAD && tid < 256) {
        int t = tid - 192;
        ecb1s[t] = ec_b1[t];
        ecw2s[t] = ec_w2[t];
    }
    __syncthreads();

    float d2[8][4];
    #pragma unroll
    for (int nt = 0; nt < 8; ++nt)
        #pragma unroll
        for (int j = 0; j < 4; ++j) d2[nt][j] = 0.f;

    // UV prefetch pipeline: nb holds loads for current hc
    float2 nb[8];
    {
        int c0 = lc * 2, c1 = c0 + 8;
        nb[0] = *(const float2*)(up0 + c0); nb[1] = *(const float2*)(vp0 + c0);
        nb[2] = *(const float2*)(up1 + c0); nb[3] = *(const float2*)(vp1 + c0);
        nb[4] = *(const float2*)(up0 + c1); nb[5] = *(const float2*)(vp0 + c1);
        nb[6] = *(const float2*)(up1 + c1); nb[7] = *(const float2*)(vp1 + c1);
    }

    #pragma unroll
    for (int hc = 0; hc < 8; ++hc) {
        float2 nn[8];
        if (hc < 7) {
            int c0 = (hc + 1) * 16 + lc * 2, c1 = c0 + 8;
            nn[0] = *(const float2*)(up0 + c0); nn[1] = *(const float2*)(vp0 + c0);
            nn[2] = *(const float2*)(up1 + c0); nn[3] = *(const float2*)(vp1 + c0);
            nn[4] = *(const float2*)(up0 + c1); nn[5] = *(const float2*)(vp0 + c1);
            nn[6] = *(const float2*)(up1 + c1); nn[7] = *(const float2*)(vp1 + c1);
        }

        // layer-1 pair init from UV
        float d1a[4], d1b[4];
        d1a[0] = nb[0].x + nb[1].x; d1a[1] = nb[0].y + nb[1].y;
        d1a[2] = nb[2].x + nb[3].x; d1a[3] = nb[2].y + nb[3].y;
        d1b[0] = nb[4].x + nb[5].x; d1b[1] = nb[4].y + nb[5].y;
        d1b[2] = nb[6].x + nb[7].x; d1b[3] = nb[6].y + nb[7].y;

        // layer-1: + ef @ W1c columns for this pair
        #pragma unroll
        for (int kc = 0; kc < 4; ++kc) {
            uint4 wA = w1cf[(kc * 16 + 2 * hc) * 32 + lane];
            mma_f16(d1a, efah[kc], wA.x, wA.y);
            mma_f16(d1a, efal[kc], wA.x, wA.y);
            mma_f16(d1a, efah[kc], wA.z, wA.w);
            uint4 wB = w1cf[(kc * 16 + 2 * hc + 1) * 32 + lane];
            mma_f16(d1b, efah[kc], wB.x, wB.y);
            mma_f16(d1b, efal[kc], wB.x, wB.y);
            mma_f16(d1b, efah[kc], wB.z, wB.w);
        }

        // layer-2: relu(+b1) -> A-frag chunk hc -> accumulate into d2
        float2 bia = *(float2*)&b1s[hc * 16 + lc * 2];
        float2 bib = *(float2*)&b1s[hc * 16 + 8 + lc * 2];
        float h00 = fmaxf(d1a[0] + bia.x, 0.f);
        float h01 = fmaxf(d1a[1] + bia.y, 0.f);
        float h10 = fmaxf(d1a[2] + bia.x, 0.f);
        float h11 = fmaxf(d1a[3] + bia.y, 0.f);
        float h20 = fmaxf(d1b[0] + bib.x, 0.f);
        float h21 = fmaxf(d1b[1] + bib.y, 0.f);
        float h30 = fmaxf(d1b[2] + bib.x, 0.f);
        float h31 = fmaxf(d1b[3] + bib.y, 0.f);
        unsigned ah[4], al[4];
        split2(h00, h01, ah[0], al[0]);
        split2(h10, h11, ah[1], al[1]);
        split2(h20, h21, ah[2], al[2]);
        split2(h30, h31, ah[3], al[3]);
        #pragma unroll
        for (int nt = 0; nt < 8; ++nt) {
            uint4 w = w2f[(hc * 8 + nt) * 32 + lane];
            mma_f16(d2[nt], ah, w.x, w.y);
            mma_f16(d2[nt], al, w.x, w.y);
            mma_f16(d2[nt], ah, w.z, w.w);
        }

        #pragma unroll
        for (int j = 0; j < 8; ++j) nb[j] = nn[j];
    }

    // ---- epilogue ----
    {
        float* ag0 = aggr + (size_t)tg0 * 64;
        float* ag1 = aggr + (size_t)tg1 * 64;
        #pragma unroll
        for (int nt = 0; nt < 8; ++nt) {
            int col = nt * 8 + lc * 2;
            d2[nt][0] += b2s[col]; d2[nt][1] += b2s[col + 1];
            d2[nt][2] += b2s[col]; d2[nt][3] += b2s[col + 1];
            float2 v0 = make_float2(d2[nt][0], d2[nt][1]);
            float2 v1 = make_float2(d2[nt][2], d2[nt][3]);
            if (HEAD) {
                *(float2*)(ef32 + g0 + col) = v0;
                *(float2*)(ef32 + g1 + col) = v1;
            } else {
                unsigned hi0, lo0, hi1, lo1;
                split2(v0.x, v0.y, hi0, lo0);
                split2(v1.x, v1.y, hi1, lo1);
                *(unsigned*)(efh + g0 + col) = hi0;
                *(unsigned*)(efl + g0 + col) = lo0;
                *(unsigned*)(efh + g1 + col) = hi1;
                *(unsigned*)(efl + g1 + col) = lo1;
            }
            atomicAdd((float2*)(ag0 + col), v0);
            atomicAdd((float2*)(ag1 + col), v1);
        }
    }

    if (HEAD) {
        float dh[8][4];
        #pragma unroll
        for (int nt = 0; nt < 8; ++nt)
            #pragma unroll
            for (int j = 0; j < 4; ++j) dh[nt][j] = 0.f;

        #pragma unroll
        for (int kc = 0; kc < 4; ++kc) {
            unsigned ah[4], al[4];
            afrag_from_regs(d2[2 * kc], d2[2 * kc + 1], ah, al);
            #pragma unroll
            for (int nt = 0; nt < 8; ++nt) {
                uint4 w = ec1f[(kc * 8 + nt) * 32 + lane];
                mma_f16(dh[nt], ah, w.x, w.y);
                mma_f16(dh[nt], al, w.x, w.y);
                mma_f16(dh[nt], ah, w.z, w.w);
            }
        }

        float s0 = 0.f, s1 = 0.f;
        #pragma unroll
        for (int nt = 0; nt < 8; ++nt) {
            int col = nt * 8 + lc * 2;
            float w0 = ecw2s[col], w1v = ecw2s[col + 1];
            float bc0 = ecb1s[col], bc1 = ecb1s[col + 1];
            s0 += fmaxf(dh[nt][0] + bc0, 0.f) * w0 + fmaxf(dh[nt][1] + bc1, 0.f) * w1v;
            s1 += fmaxf(dh[nt][2] + bc0, 0.f) * w0 + fmaxf(dh[nt][3] + bc1, 0.f) * w1v;
        }
        s0 += __shfl_xor_sync(0xffffffffu, s0, 1);
        s0 += __shfl_xor_sync(0xffffffffu, s0, 2);
        s1 += __shfl_xor_sync(0xffffffffu, s1, 1);
        s1 += __shfl_xor_sync(0xffffffffu, s1, 2);
        if (lc == 0) {
            float bb = ec_b2[0];
            epred[e0 + row0] = s0 + bb;
            epred[e0 + row1] = s1 + bb;
        }
    }
}

// =====================================================================
// nu update (+ zero aggr; optional mirror write of nf)
// =====================================================================
__global__ __launch_bounds__(256) void nu_mma_kernel(
    float* __restrict__ nf, float* __restrict__ aggr,
    const uint4* __restrict__ wf, const float* __restrict__ b,
    float* __restrict__ nf_out, int rows)
{
    __shared__ __half A_hi[128 * E_STRIDE];
    __shared__ __half A_lo[128 * E_STRIDE];
    __shared__ float bs[64];

    const int tid = threadIdx.x, wid = tid >> 5, lane = tid & 31;
    const int r0 = blockIdx.x * 128;
    if (tid < 64) bs[tid] = b[tid];

    const int m0 = wid * 16;
    const int lr = lane >> 2, lc = lane & 3;

    float d[8][4];
    #pragma unroll
    for (int nt = 0; nt < 8; ++nt)
        #pragma unroll
        for (int j = 0; j < 4; ++j) d[nt][j] = 0.f;

    #pragma unroll
    for (int stage = 0; stage < 2; ++stage) {
        stage_split64(stage ? aggr : nf, r0, rows, A_hi, A_lo, tid);
        __syncthreads();
        #pragma unroll
        for (int kc = 0; kc < 4; ++kc) {
            unsigned ah[4], al[4];
            load_afrag(A_hi, A_lo, m0 + lr, kc * 16 + lc * 2, ah, al);
            #pragma unroll
            for (int nt = 0; nt < 8; ++nt) {
                uint4 w = wf[((stage * 4 + kc) * 8 + nt) * 32 + lane];
                mma_f16(d[nt], ah, w.x, w.y);
                mma_f16(d[nt], al, w.x, w.y);
                mma_f16(d[nt], ah, w.z, w.w);
            }
        }
        __syncthreads();
    }

    int row0 = r0 + m0 + lr, row1 = row0 + 8;
    #pragma unroll
    for (int nt = 0; nt < 8; ++nt) {
        int col = nt * 8 + lc * 2;
        if (row0 < rows) {
            float2 v = make_float2(d[nt][0] + bs[col], d[nt][1] + bs[col + 1]);
            *(float2*)(nf + (size_t)row0 * 64 + col) = v;
            if (nf_out) *(float2*)(nf_out + (size_t)row0 * 64 + col) = v;
        }
        if (row1 < rows) {
            float2 v = make_float2(d[nt][2] + bs[col], d[nt][3] + bs[col + 1]);
            *(float2*)(nf + (size_t)row1 * 64 + col) = v;
            if (nf_out) *(float2*)(nf_out + (size_t)row1 * 64 + col) = v;
        }
    }

    {
        int r = r0 + (tid >> 1);
        if (r < rows) {
            float4* zp = (float4*)(aggr + (size_t)r * 64 + (tid & 1) * 32);
            #pragma unroll
            for (int j = 0; j < 8; ++j) zp[j] = make_float4(0.f, 0.f, 0.f, 0.f);
        }
    }
}

// =====================================================================
// node encoder: 64->64->64, fp32 out
// =====================================================================
__global__ __launch_bounds__(256) void enc_mma_kernel(
    const float* __restrict__ X,
    const uint4* __restrict__ w1f, const float* __restrict__ b1,
    const uint4* __restrict__ w2f, const float* __restrict__ b2,
    float* __restrict__ Y, int rows)
{
    __shared__ __half A_hi[128 * E_STRIDE];
    __shared__ __half A_lo[128 * E_STRIDE];
    __shared__ float b1s[64], b2s[64];

    const int tid = threadIdx.x, wid = tid >> 5, lane = tid & 31;
    const int r0 = blockIdx.x * 128;

    if (tid < 64) b1s[tid] = b1[tid];
    else if (tid < 128) b2s[tid - 64] = b2[tid - 64];

    stage_split64(X, r0, rows, A_hi, A_lo, tid);
    __syncthreads();

    const int m0 = wid * 16;
    const int lr = lane >> 2, lc = lane & 3;

    float d1[8][4];
    #pragma unroll
    for (int nt = 0; nt < 8; ++nt)
        #pragma unroll
        for (int j = 0; j < 4; ++j) d1[nt][j] = 0.f;

    #pragma unroll
    for (int kc = 0; kc < 4; ++kc) {
        unsigned ah[4], al[4];
        load_afrag(A_hi, A_lo, m0 + lr, kc * 16 + lc * 2, ah, al);
        #pragma unroll
        for (int nt = 0; nt < 8; ++nt) {
            uint4 w = w1f[(kc * 8 + nt) * 32 + lane];
            mma_f16(d1[nt], ah, w.x, w.y);
            mma_f16(d1[nt], al, w.x, w.y);
            mma_f16(d1[nt], ah, w.z, w.w);
        }
    }

    float d2[8][4];
    #pragma unroll
    for (int nt = 0; nt < 8; ++nt)
        #pragma unroll
        for (int j = 0; j < 4; ++j) d2[nt][j] = 0.f;

    #pragma unroll
    for (int kc = 0; kc < 4; ++kc) {
        float2 bia = *(float2*)&b1s[kc * 16 + lc * 2];
        float2 bib = *(float2*)&b1s[kc * 16 + 8 + lc * 2];
        float h00 = fmaxf(d1[2 * kc][0] + bia.x, 0.f);
        float h01 = fmaxf(d1[2 * kc][1] + bia.y, 0.f);
        float h10 = fmaxf(d1[2 * kc][2] + bia.x, 0.f);
        float h11 = fmaxf(d1[2 * kc][3] + bia.y, 0.f);
        float h20 = fmaxf(d1[2 * kc + 1][0] + bib.x, 0.f);
        float h21 = fmaxf(d1[2 * kc + 1][1] + bib.y, 0.f);
        float h30 = fmaxf(d1[2 * kc + 1][2] + bib.x, 0.f);
        float h31 = fmaxf(d1[2 * kc + 1][3] + bib.y, 0.f);
        unsigned ah[4], al[4];
        split2(h00, h01, ah[0], al[0]);
        split2(h10, h11, ah[1], al[1]);
        split2(h20, h21, ah[2], al[2]);
        split2(h30, h31, ah[3], al[3]);
        #pragma unroll
        for (int nt = 0; nt < 8; ++nt) {
            uint4 w = w2f[(kc * 8 + nt) * 32 + lane];
            mma_f16(d2[nt], ah, w.x, w.y);
            mma_f16(d2[nt], al, w.x, w.y);
            mma_f16(d2[nt], ah, w.z, w.w);
        }
    }

    int row0 = r0 + m0 + lr, row1 = row0 + 8;
    #pragma unroll
    for (int nt = 0; nt < 8; ++nt) {
        int col = nt * 8 + lc * 2;
        if (row0 < rows)
            *(float2*)(Y + (size_t)row0 * 64 + col) =
                make_float2(d2[nt][0] + b2s[col], d2[nt][1] + b2s[col + 1]);
        if (row1 < rows)
            *(float2*)(Y + (size_t)row1 * 64 + col) =
                make_float2(d2[nt][2] + b2s[col], d2[nt][3] + b2s[col + 1]);
    }
}

// =====================================================================
// fp32 linear (ce embedding only)
// =====================================================================
__global__ __launch_bounds__(256) void linear_kernel(
    const float* __restrict__ A0,
    const float* __restrict__ W, const float* __restrict__ B,
    float* __restrict__ Y, int rows)
{
    __shared__ float As[4096];
    __shared__ float Bs[4096];
    const int tid = threadIdx.x;
    const int tx = tid & 15, ty = tid >> 4;
    const int r0 = blockIdx.x * 64;
    const int rl = tid >> 2, ql = tid & 3;

    float acc[4][4] = {};
    {
        int gr = min(r0 + rl, rows - 1);
        const float4* rp = (const float4*)(A0 + (size_t)gr * 64);
        #pragma unroll
        for (int j = 0; j < 4; ++j) {
            float4 v = rp[ql * 4 + j];
            int k = (ql * 4 + j) * 4;
            As[(k + 0) * 64 + rl] = v.x; As[(k + 1) * 64 + rl] = v.y;
            As[(k + 2) * 64 + rl] = v.z; As[(k + 3) * 64 + rl] = v.w;
        }
        const float4* wp = (const float4*)(W + (size_t)rl * 64) + ql * 4;
        float4* bp = (float4*)(Bs + rl * 64) + ql * 4;
        #pragma unroll
        for (int j = 0; j < 4; ++j) bp[j] = wp[j];
    }
    __syncthreads();
    #pragma unroll 8
    for (int k = 0; k < 64; ++k) {
        float4 av = *(const float4*)(As + k * 64 + ty * 4);
        float4 bv = *(const float4*)(Bs + k * 64 + tx * 4);
        float a[4] = {av.x, av.y, av.z, av.w};
        float b[4] = {bv.x, bv.y, bv.z, bv.w};
        #pragma unroll
        for (int m = 0; m < 4; ++m)
            #pragma unroll
            for (int j = 0; j < 4; ++j) acc[m][j] = fmaf(a[m], b[j], acc[m][j]);
    }
    float bv4[4] = {B[tx * 4 + 0], B[tx * 4 + 1], B[tx * 4 + 2], B[tx * 4 + 3]};
    #pragma unroll
    for (int m = 0; m < 4; ++m) {
        int r = r0 + ty * 4 + m;
        if (r < rows) {
            float4 o;
            o.x = acc[m][0] + bv4[0]; o.y = acc[m][1] + bv4[1];
            o.z = acc[m][2] + bv4[2]; o.w = acc[m][3] + bv4[3];
            *(float4*)(Y + (size_t)r * 64 + tx * 4) = o;
        }
    }
}

// =====================================================================
// node heads: 64 -> 64(relu) -> OUT, one warp per row
// =====================================================================
template <int OUT>
__global__ __launch_bounds__(256) void head_kernel(
    const float* __restrict__ X,
    const float* __restrict__ W1, const float* __restrict__ B1,
    const float* __restrict__ W2, const float* __restrict__ B2,
    float* __restrict__ Y, int* __restrict__ amax, int rows)
{
    __shared__ float sh[8][64];
    const int lane = threadIdx.x & 31, w = threadIdx.x >> 5;
    const int row = blockIdx.x * 8 + w;
    if (row >= rows) return;

    sh[w][lane]      = X[(size_t)row * 64 + lane];
    sh[w][lane + 32] = X[(size_t)row * 64 + lane + 32];
    __syncwarp();

    float h0 = B1[lane], h1 = B1[lane + 32];
    #pragma unroll
    for (int k = 0; k < 64; ++k) {
        float xv = sh[w][k];
        h0 = fmaf(xv, W1[k * 64 + lane], h0);
        h1 = fmaf(xv, W1[k * 64 + lane + 32], h1);
    }
    h0 = fmaxf(h0, 0.f); h1 = fmaxf(h1, 0.f);

    if (OUT == 1) {
        float s = h0 * W2[lane] + h1 * W2[lane + 32];
        #pragma unroll
        for (int off = 16; off; off >>= 1) s += __shfl_down_sync(0xffffffffu, s, off);
        if (lane == 0) Y[row] = s + B2[0];
    } else {
        __syncwarp();
        sh[w][lane] = h0; sh[w][lane + 32] = h1;
        __syncwarp();
        float bv = -INFINITY;
        int bi = 1 << 30;
        if (lane < OUT) {
            float val = B2[lane];
            #pragma unroll
            for (int k = 0; k < 64; ++k) val = fmaf(sh[w][k], W2[k * OUT + lane], val);
            Y[(size_t)row * OUT + lane] = val;
            bv = val; bi = lane;
        }
        #pragma unroll
        for (int off = 16; off; off >>= 1) {
            float ov = __shfl_down_sync(0xffffffffu, bv, off);
            int   oi = __shfl_down_sync(0xffffffffu, bi, off);
            if (ov > bv || (ov == bv && oi < bi)) { bv = ov; bi = oi; }
        }
        if (lane == 0 && amax) amax[row] = bi;
    }
}

// =====================================================================
// type-constrained scatter softmax pieces
// =====================================================================
__global__ void init_softmax_kernel(unsigned* mx, float* denom, int n) {
    int i = blockIdx.x * blockDim.x + threadIdx.x;
    if (i < n) { mx[i] = 0u; denom[i] = 0.f; }
}

__global__ __launch_bounds__(256) void scores_kernel(
    const float* __restrict__ emb, const int* __restrict__ src, const int* __restrict__ tgt,
    const int* __restrict__ types, float* __restrict__ scores, int* __restrict__ seg,
    unsigned* __restrict__ mx)
{
    const int lane = threadIdx.x & 31, w = threadIdx.x >> 5;
    const int e = blockIdx.x * 8 + w;
    if (e >= NE) return;
    int s = src[e], t = tgt[e];
    const float* es = emb + (size_t)s * 64;
    const float* et = emb + (size_t)t * 64;
    float p = es[lane] * et[lane] + es[lane + 32] * et[lane + 32];
    #pragma unroll
    for (int off = 16; off; off >>= 1) p += __shfl_down_sync(0xffffffffu, p, off);
    if (lane == 0) {
        scores[e] = p;
        int sg = t * NT + types[s];
        seg[e] = sg;
        atomicMax(&mx[sg], ordf(p));
    }
}

__global__ void ex_kernel(float* __restrict__ scores, const int* __restrict__ seg,
                          const unsigned* __restrict__ mx, float* __restrict__ denom, int n) {
    int i = blockIdx.x * blockDim.x + threadIdx.x;
    if (i < n) {
        int sg = seg[i];
        float exv = expf(scores[i] - deord(mx[sg]));
        scores[i] = exv;
        atomicAdd(&denom[sg], exv);
    }
}

__global__ void final_kernel(const float* __restrict__ ex, const int* __restrict__ seg,
                             const float* __restrict__ denom, const float* __restrict__ epred,
                             float* __restrict__ out_edge, int n) {
    int i = blockIdx.x * blockDim.x + threadIdx.x;
    if (i < n) {
        float sig = 1.f / (1.f + expf(-epred[i]));
        out_edge[i] = ex[i] / denom[seg[i]] * sig;
    }
}

__global__ void zero_kernel(float* p, int n) {
    int i = blockIdx.x * blockDim.x + threadIdx.x;
    if (i < n) p[i] = 0.f;
}

// =====================================================================
// launch
// =====================================================================
extern "C" void kernel_launch(void* const* d_in, const int* in_sizes, int n_in,
                              void* d_out, int out_size)
{
    const float* x         = (const float*)d_in[0];
    const float* edge_attr = (const float*)d_in[1];
    const int*   eidx      = (const int*)d_in[2];
    const int*   src = eidx;
    const int*   tgt = eidx + NE;
    const float *ne_w1 = (const float*)d_in[4],  *ne_b1 = (const float*)d_in[5];
    const float *ne_w2 = (const float*)d_in[6],  *ne_b2 = (const float*)d_in[7];
    const float *ee_w1 = (const float*)d_in[8],  *ee_b1 = (const float*)d_in[9];
    const float *ee_w2 = (const float*)d_in[10], *ee_b2 = (const float*)d_in[11];
    const float *me_w1 = (const float*)d_in[12], *me_b1 = (const float*)d_in[13];
    const float *me_w2 = (const float*)d_in[14], *me_b2 = (const float*)d_in[15];
    const float *nu_w1 = (const float*)d_in[16], *nu_b1 = (const float*)d_in[17];
    const float *ec_w1 = (const float*)d_in[18], *ec_b1 = (const float*)d_in[19];
    const float *ec_w2 = (const float*)d_in[20], *ec_b2 = (const float*)d_in[21];
    const float *nc_w1 = (const float*)d_in[22], *nc_b1 = (const float*)d_in[23];
    const float *nc_w2 = (const float*)d_in[24], *nc_b2 = (const float*)d_in[25];
    const float *cl_w1 = (const float*)d_in[26], *cl_b1 = (const float*)d_in[27];
    const float *cl_w2 = (const float*)d_in[28], *cl_b2 = (const float*)d_in[29];
    const float *ce_w  = (const float*)d_in[30], *ce_b  = (const float*)d_in[31];

    float* out = (float*)d_out;
    float* out_edge = out;
    float* out_node = out + NE;
    float* out_cls  = out_node + NN;
    float* out_nf   = out_cls + (size_t)NN * NT;
    float* out_ef   = out_nf + (size_t)NN * 64;

    float *p_nf, *p_aggr, *p_uv, *p_emb, *p_scores, *p_denom, *p_epred;
    __half *p_efh, *p_efl;
    int *p_seg, *p_types;
    unsigned* p_mx;
    uint4 *p_w1cf, *p_w2f, *p_wcatf, *p_nuf, *p_ne1f, *p_ne2f, *p_ee1f, *p_ee2f, *p_ec1f;
    cudaGetSymbolAddress((void**)&p_nf, g_nf);
    cudaGetSymbolAddress((void**)&p_aggr, g_aggr);
    cudaGetSymbolAddress((void**)&p_uv, g_uv);
    cudaGetSymbolAddress((void**)&p_efh, g_efh);
    cudaGetSymbolAddress((void**)&p_efl, g_efl);
    cudaGetSymbolAddress((void**)&p_emb, g_emb);
    cudaGetSymbolAddress((void**)&p_scores, g_scores);
    cudaGetSymbolAddress((void**)&p_seg, g_seg);
    cudaGetSymbolAddress((void**)&p_epred, g_epred);
    cudaGetSymbolAddress((void**)&p_mx, g_mx);
    cudaGetSymbolAddress((void**)&p_denom, g_denom);
    cudaGetSymbolAddress((void**)&p_types, g_types);
    cudaGetSymbolAddress((void**)&p_w1cf, g_w1cf);
    cudaGetSymbolAddress((void**)&p_w2f, g_w2f);
    cudaGetSymbolAddress((void**)&p_wcatf, g_wcatf);
    cudaGetSymbolAddress((void**)&p_nuf, g_nuf);
    cudaGetSymbolAddress((void**)&p_ne1f, g_ne1f);
    cudaGetSymbolAddress((void**)&p_ne2f, g_ne2f);
    cudaGetSymbolAddress((void**)&p_ee1f, g_ee1f);
    cudaGetSymbolAddress((void**)&p_ee2f, g_ee2f);
    cudaGetSymbolAddress((void**)&p_ec1f, g_ec1f);

    // 1: all weight prep in one launch
    prep_all_kernel<<<60, 256>>>(me_w1, me_w2, nu_w1, ne_w1, ne_w2, ee_w1, ee_w2, ec_w1,
                                 p_w1cf, p_w2f, p_wcatf, p_nuf,
                                 p_ne1f, p_ne2f, p_ee1f, p_ee2f, p_ec1f);

    // 2: node encoder
    enc_mma_kernel<<<(NN + 127) / 128, 256>>>(x, p_ne1f, ne_b1, p_ne2f, ne_b2, p_nf, NN);

    // 3: zero aggr once (subsequent zeroing fused into nu)
    zero_kernel<<<(NN * 64 + 255) / 256, 256>>>(p_aggr, NN * 64);

    // step 1: uv + FUSED edge-encoder+msg + nu
    uv_mma_kernel<<<dim3((NN + 127) / 128, 2), 256>>>(p_nf, p_wcatf, p_uv, NN);
    encmsg_mma_kernel<<<NE / 128, 256>>>(edge_attr, p_uv, p_efh, p_efl, src, tgt,
                                         p_ee1f, ee_b1, p_ee2f, ee_b2,
                                         p_w1cf, me_b1, p_w2f, me_b2, p_aggr);
    nu_mma_kernel<<<(NN + 127) / 128, 256>>>(p_nf, p_aggr, p_nuf, nu_b1, nullptr, NN);

    // step 2
    uv_mma_kernel<<<dim3((NN + 127) / 128, 2), 256>>>(p_nf, p_wcatf, p_uv, NN);
    msg_mma_kernel<false><<<NE / 128, 256>>>(p_uv, p_efh, p_efl, nullptr, src, tgt,
                                             p_w1cf, me_b1, p_w2f, me_b2, p_aggr,
                                             nullptr, nullptr, nullptr, nullptr, nullptr);
    nu_mma_kernel<<<(NN + 127) / 128, 256>>>(p_nf, p_aggr, p_nuf, nu_b1, nullptr, NN);

    // step 3 (HEAD fused; last nu mirrors nf into out_nf)
    uv_mma_kernel<<<dim3((NN + 127) / 128, 2), 256>>>(p_nf, p_wcatf, p_uv, NN);
    msg_mma_kernel<true><<<NE / 128, 256>>>(p_uv, p_efh, p_efl, out_ef, src, tgt,
                                            p_w1cf, me_b1, p_w2f, me_b2, p_aggr,
                                            p_ec1f, ec_b1, ec_w2, ec_b2, p_epred);
    nu_mma_kernel<<<(NN + 127) / 128, 256>>>(p_nf, p_aggr, p_nuf, nu_b1, out_nf, NN);

    // node heads
    head_kernel<1><<<(NN + 7) / 8, 256>>>(p_nf, nc_w1, nc_b1, nc_w2, nc_b2, out_node, nullptr, NN);
    head_kernel<NT><<<(NN + 7) / 8, 256>>>(p_nf, cl_w1, cl_b1, cl_w2, cl_b2, out_cls, p_types, NN);

    // node embedding + type-constrained scatter softmax
    linear_kernel<<<(NN + 63) / 64, 256>>>(p_nf, ce_w, ce_b, p_emb, NN);
    init_softmax_kernel<<<(NN * NT + 255) / 256, 256>>>(p_mx, p_denom, NN * NT);
    scores_kernel<<<(NE + 7) / 8, 256>>>(p_emb, src, tgt, p_types, p_scores, p_seg, p_mx);
    ex_kernel<<<(NE + 255) / 256, 256>>>(p_scores, p_seg, p_mx, p_denom, NE);
    final_kernel<<<(NE + 255) / 256, 256>>>(p_scores, p_seg, p_denom, p_epred, out_edge, NE);
}